// round 11
// baseline (speedup 1.0000x reference)
#include <cuda_runtime.h>
#include <math.h>

#define LOG_SQRT_2PI 0.91893853320467274178f  // 0.5*log(2*pi)

// sync/scratch globals — zero-initialized at module load; the kernel's last
// block resets them to zero so every graph replay starts clean.
__device__ float          g_partials[256];
__device__ int            g_counter;        // # prior blocks that published a partial
__device__ volatile int   g_flag;           // prior ready
__device__ volatile float g_prior;
__device__ int            g_done;           // # blocks fully finished

// ---------------------------------------------------------------------------
// Fused kernel: grid = B blocks x 256 threads.
//   Phase 1 (blocks 0..nPriorBlocks-1): per-sample prior NLL -> partials; the
//     last prior block to arrive reduces partials -> g_prior, sets g_flag.
//   Phase 2 (all blocks): row MSE. Fast path for S4==1024: fully unrolled,
//     all 8 LDG.128 front-batched per thread (MLP_p1=8) with 4 independent
//     accumulators. Writer thread waits on g_flag (already set by then).
//   Epilogue: last block to finish resets the sync globals for next replay.
// ---------------------------------------------------------------------------
__global__ void fused_posterior_kernel(const float*  __restrict__ predAbun,
                                       const float*  __restrict__ sigmaPrior,
                                       const float4* __restrict__ yReal4,
                                       const float4* __restrict__ ySim4,
                                       float* __restrict__ out,
                                       int B, int S4, float scale, float invB,
                                       int nPriorBlocks)
{
    const int row  = blockIdx.x;
    const int tid  = threadIdx.x;
    const int lane = tid & 31;
    const int wid  = tid >> 5;

    __shared__ float warp_sums[8];

    // ---------------- Phase 1: prior (first nPriorBlocks blocks only) -------
    if (row < nPriorBlocks) {
        int s = row * 256 + tid;
        float acc = 0.0f;
        if (s < B) {
            float p[7], sg[7];
#pragma unroll
            for (int i = 0; i < 7; ++i) {
                p[i]  = predAbun[s * 7 + i];
                sg[i] = sigmaPrior[s * 7 + i];
            }
            // molecule order: O2, N2, H2, CO2, H2O, CH4, NH3
            float H = 2.0f * p[2] + 2.0f * p[4] + 3.0f * p[6] + 4.0f * p[5];
            float C = p[3] + p[5];
            float O = 2.0f * p[0] + 2.0f * p[3] + p[4];
            float N = 2.0f * p[1] + p[6];

            float mu[7] = {0.f, 0.f, 0.f, 0.f, 0.f, 0.f, 0.f};

            bool condA = H > 2.0f * O + 4.0f * C;
            if (condA) {
                if (3.0f * N < H - 2.0f * O - 4.0f * C) {
                    float D = H - N - 2.0f * C;
                    float inv = __fdividef(1.0f, D);
                    mu[2] = (H - 2.0f * O - 4.0f * C - 3.0f * N) * inv;
                    mu[4] = 2.0f * O * inv;
                    mu[5] = 2.0f * C * inv;
                    mu[6] = 2.0f * N * inv;
                } else {
                    float D = H + 2.0f * C + 3.0f * N + 4.0f * O;
                    float inv = __fdividef(1.0f, D);
                    mu[1] = (3.0f * N + 4.0f * C + 2.0f * O - H) * inv;
                    mu[4] = 6.0f * O * inv;
                    mu[5] = 6.0f * C * inv;
                    mu[6] = (2.0f * H - 8.0f * C - 4.0f * O) * inv;
                }
            } else if (2.0f * O > H + 4.0f * C) {
                float D = H + 2.0f * O + 2.0f * N;
                float inv = __fdividef(1.0f, D);
                mu[0] = (2.0f * O - H - 4.0f * C) * inv;
                mu[1] = 2.0f * N * inv;
                mu[3] = 4.0f * C * inv;
                mu[4] = 2.0f * H * inv;
            } else if (fabsf(H + C + O + N - 1.0f) < 1e-3f) {
                float D1 = H + 2.0f * O + 2.0f * N;
                float D2 = 2.0f * H + 4.0f * O + 4.0f * N;
                float i1 = __fdividef(1.0f, D1);
                float i2 = __fdividef(1.0f, D2);
                mu[1] = 2.0f * N * i1;
                mu[3] = (2.0f * O + 4.0f * C - H) * i2;
                mu[4] = (H + 2.0f * O - 4.0f * C) * i1;
                mu[5] = (H - 2.0f * O + 4.0f * C) * i2;
            }
            // else unclassified -> mu stays 0

            // sum of logs == log of product (sigmas in [0.1, 0.6], safe)
            float prod = sg[0] * sg[1] * sg[2] * sg[3] * sg[4] * sg[5] * sg[6];
            acc = 7.0f * LOG_SQRT_2PI + __logf(prod);
#pragma unroll
            for (int i = 0; i < 7; ++i) {
                float d = p[i] - mu[i];
                acc += __fdividef(0.5f * d * d, sg[i] * sg[i]);
            }
        }

        // block reduce (8 warps)
#pragma unroll
        for (int off = 16; off > 0; off >>= 1)
            acc += __shfl_down_sync(0xFFFFFFFFu, acc, off);
        if (lane == 0) warp_sums[wid] = acc;
        __syncthreads();
        if (tid == 0) {
            float v = 0.0f;
#pragma unroll
            for (int w = 0; w < 8; ++w) v += warp_sums[w];
            g_partials[row] = v;
            __threadfence();
            int c = atomicAdd(&g_counter, 1);
            if (c == nPriorBlocks - 1) {
                float t = 0.0f;
                for (int i = 0; i < nPriorBlocks; ++i) t += g_partials[i];
                g_prior = t * invB;
                __threadfence();
                g_flag = 1;
            }
        }
        __syncthreads();  // shared memory reused below
    }

    // ---------------- Phase 2: row MSE (all blocks) -------------------------
    const float4* r = yReal4 + (long long)row * S4;
    const float4* s = ySim4  + (long long)row * S4;

    float acc;
    if (S4 == 1024) {
        // Fast path: 4 fully-unrolled iterations, all 8 LDG.128 front-batched.
        float4 a0, a1, a2, a3, b0, b1, b2, b3;
        a0 = __ldg(r + tid);
        a1 = __ldg(r + tid + 256);
        a2 = __ldg(r + tid + 512);
        a3 = __ldg(r + tid + 768);
        b0 = __ldg(s + tid);
        b1 = __ldg(s + tid + 256);
        b2 = __ldg(s + tid + 512);
        b3 = __ldg(s + tid + 768);

        float c0 = 0.f, c1 = 0.f, c2 = 0.f, c3 = 0.f;
        float d;
        d = a0.x - b0.x; c0 = fmaf(d, d, c0);
        d = a0.y - b0.y; c1 = fmaf(d, d, c1);
        d = a0.z - b0.z; c2 = fmaf(d, d, c2);
        d = a0.w - b0.w; c3 = fmaf(d, d, c3);
        d = a1.x - b1.x; c0 = fmaf(d, d, c0);
        d = a1.y - b1.y; c1 = fmaf(d, d, c1);
        d = a1.z - b1.z; c2 = fmaf(d, d, c2);
        d = a1.w - b1.w; c3 = fmaf(d, d, c3);
        d = a2.x - b2.x; c0 = fmaf(d, d, c0);
        d = a2.y - b2.y; c1 = fmaf(d, d, c1);
        d = a2.z - b2.z; c2 = fmaf(d, d, c2);
        d = a2.w - b2.w; c3 = fmaf(d, d, c3);
        d = a3.x - b3.x; c0 = fmaf(d, d, c0);
        d = a3.y - b3.y; c1 = fmaf(d, d, c1);
        d = a3.z - b3.z; c2 = fmaf(d, d, c2);
        d = a3.w - b3.w; c3 = fmaf(d, d, c3);
        acc = (c0 + c1) + (c2 + c3);
    } else {
        // Generic fallback
        acc = 0.0f;
        for (int j = tid; j < S4; j += 256) {
            float4 a = __ldg(r + j);
            float4 b = __ldg(s + j);
            float d0 = a.x - b.x, d1 = a.y - b.y, d2 = a.z - b.z, d3 = a.w - b.w;
            acc = fmaf(d0, d0, acc);
            acc = fmaf(d1, d1, acc);
            acc = fmaf(d2, d2, acc);
            acc = fmaf(d3, d3, acc);
        }
    }

#pragma unroll
    for (int off = 16; off > 0; off >>= 1)
        acc += __shfl_down_sync(0xFFFFFFFFu, acc, off);
    if (lane == 0) warp_sums[wid] = acc;
    __syncthreads();

    if (tid == 0) {
        float v = 0.0f;
#pragma unroll
        for (int w = 0; w < 8; ++w) v += warp_sums[w];
        // wait for prior (set long before any block finishes 32KB of loads)
        while (g_flag == 0) { }
        float pr = g_prior;
        out[row] = v * scale + pr;

        // epilogue: last block to finish resets sync globals for next replay
        int d = atomicAdd(&g_done, 1);
        if (d == gridDim.x - 1) {
            g_counter = 0;
            g_flag    = 0;
            g_done    = 0;
        }
    }
}

// ---------------------------------------------------------------------------
// launch
// inputs (metadata order): predAbun [B,7] f32, sigmaPrior [B,7] f32,
//                          yReal [B,S] f32, ySim [B,S] f32
// output: posterior [B] f32
// ---------------------------------------------------------------------------
extern "C" void kernel_launch(void* const* d_in, const int* in_sizes, int n_in,
                              void* d_out, int out_size)
{
    const float* predAbun   = (const float*)d_in[0];
    const float* sigmaPrior = (const float*)d_in[1];
    const float* yReal      = (const float*)d_in[2];
    const float* ySim       = (const float*)d_in[3];
    float* out = (float*)d_out;

    int B  = in_sizes[0] / 7;   // 8192
    int S  = in_sizes[2] / B;   // 4096
    int S4 = S / 4;

    const float SIGMA_L = 0.1f;
    float scale = 1.0f / (2.0f * SIGMA_L * SIGMA_L * (float)S);  // folds mean over S

    int nPriorBlocks = (B + 255) / 256;  // 32 for B=8192 (g_partials holds 256)

    fused_posterior_kernel<<<B, 256>>>(predAbun, sigmaPrior,
                                       (const float4*)yReal, (const float4*)ySim,
                                       out, B, S4, scale, 1.0f / (float)B,
                                       nPriorBlocks);
}